// round 10
// baseline (speedup 1.0000x reference)
#include <cuda_runtime.h>
#include <stdint.h>

// TDGSPooling2d: gumbel-softmax hard pooling over 2x2 patches (forward = argmax).
// out[b,c,ho,wo] = x_patch[argmax_k(x_patch[k]/temp[c,ho,wo] + g_k)]
// Noise: JAX partitionable threefry: bits[i] = o0^o1,
//   (o0,o1) = threefry2x32(key=(0,42), counter=(0,i))
//
// R10: alu-pipe relief at constant instruction count. Hash tail + float
// bit-prep (xor, >>9, |0x3f800000 = 3 alu ops) replaced by
//   h0 = umulhi(x0, 2^23)   [fma pipe]  == x0 >> 9
//   h1 = umulhi(x1, 2^23)   [fma pipe]  == x1 >> 9
//   f  = (h0 ^ h1) | 0x3f800000          [one LOP3, lut 0xBE]
// (logical shift distributes over xor). Same float bits -> noise identical.
// -2 alu ops per hash (-12% alu load); R8 established mul.hi is full-rate.

#define QC 12845056u   // x element stride AND counter stride per quarter (=4*QO)
#define QO 3211264u    // output element stride per batch-quarter (8*401408)

// add on the FMA pipe: a*one + b, one==1 but unprovable by ptxas
__device__ __forceinline__ uint32_t addf(uint32_t a, uint32_t b, uint32_t one) {
    uint32_t r;
    asm("mad.lo.u32 %0, %1, %2, %3;" : "=r"(r) : "r"(a), "r"(one), "r"(b));
    return r;
}

// ---------- threefry2x32, key=(0,42), counter (0,c1) ----------
// Returns the float BITS of 1+u:  ((o0^o1)>>9) | 0x3f800000, with the
// shift+xor+or folded into 2 umulhi (fma pipe) + 1 LOP3.
// ks0 = 0, ks1 = 42, ks2 = 0x1BD11BDA ^ 0 ^ 42 = 0x1BD11BF0
__device__ __forceinline__ uint32_t tf_fbits_0_42(uint32_t c1, uint32_t one,
                                                  uint32_t k23) {
    const uint32_t ks1 = 42u;
    const uint32_t ks2 = 0x1BD11BF0u;
    uint32_t x1 = addf(c1, ks1, one);
    uint32_t x0 = x1;                 // round-0 add with x0 = c0+ks0 = 0
    x1 = __funnelshift_l(x1, x1, 13) ^ x0;
#define R(r) { x0 = addf(x1, x0, one); x1 = __funnelshift_l(x1, x1, (r)) ^ x0; }
    R(15) R(26) R(6)
    x0 = addf(x0, ks1, one);      x1 = addf(x1, ks2 + 1u, one);
    R(17) R(29) R(16) R(24)
    x0 = addf(x0, ks2, one);      x1 = addf(x1, 2u, one);        // ks0+2
    R(13) R(15) R(26) R(6)
    /* x0 += ks0 (=0) */          x1 = addf(x1, ks1 + 3u, one);
    R(17) R(29) R(16) R(24)
    x0 = addf(x0, ks1, one);      x1 = addf(x1, ks2 + 4u, one);
    R(13) R(15) R(26) R(6)
    x0 = addf(x0, ks2, one);      x1 = addf(x1, 5u, one);        // ks0+5
#undef R
    uint32_t h0, h1, f;
    asm("mul.hi.u32 %0, %1, %2;" : "=r"(h0) : "r"(x0), "r"(k23));  // x0>>9
    asm("mul.hi.u32 %0, %1, %2;" : "=r"(h1) : "r"(x1), "r"(k23));  // x1>>9
    // (h0 ^ h1) | 0x3f800000 : lut (a^b)|c = 0xBE
    asm("lop3.b32 %0, %1, %2, %3, 0xBE;"
        : "=r"(f) : "r"(h0), "r"(h1), "r"(0x3f800000u));
    return f;
}

// ---------- gumbel in base-2 score domain (R9 form, verified) ----------
// Input: float bits of 1+u. Returns L = log2(-log2(u)); caller's score is
// w = fmaf(x, rt2, -L). Path select:
//   s = u-1 <= -2^-7 : nl2 = -__log2f(u)     (MUFU, rel err <= 3.2e-5)
//   s in (-2^-7, 0]  : degree-3 log1p poly, coeffs pre-scaled by 1/ln2
// No u=0 clamp: w -> -inf there, never wins; reference's clamped lane also
// never wins (P ~ 1e-60). Argmax unchanged.
__device__ __forceinline__ float log2_negl2_u(uint32_t fbits) {
    const float C1 = 1.44269504088896340736f;   // 1/ln2
    const float C2 = -0.72134752044448170368f;  // -1/(2 ln2)
    const float C3 = 0.48089834696298780245f;   // 1/(3 ln2)
    float u = __uint_as_float(fbits) - 1.0f;
    float nl_m = -__log2f(u);
    float s = u - 1.0f;                          // exact for u in [0.5,1]
    float p = fmaf(C3, s, C2);
    p = fmaf(p, s, C1);
    float nl_p = -s * p;
    float nl = (s > -0.0078125f) ? nl_p : nl_m;
    return __log2f(nl);
}

__device__ __forceinline__ float argmax_pick(float2 v0, float2 v1, float rt2,
                                             uint32_t r0, uint32_t r1,
                                             uint32_t r2, uint32_t r3) {
    float wb = fmaf(v0.x, rt2, -log2_negl2_u(r0));
    float xb = v0.x;
    float w;
    w = fmaf(v0.y, rt2, -log2_negl2_u(r1)); if (w > wb) { wb = w; xb = v0.y; }
    w = fmaf(v1.x, rt2, -log2_negl2_u(r2)); if (w > wb) { wb = w; xb = v1.x; }
    w = fmaf(v1.y, rt2, -log2_negl2_u(r3)); if (w > wb) { wb = w; xb = v1.y; }
    return xb;
}

__global__ __launch_bounds__(256)
void tdgs_pool_kernel(const float* __restrict__ x,
                      const float* __restrict__ temp,
                      float* __restrict__ out) {
    uint32_t one = gridDim.y;                       // == 1, opaque to ptxas
    uint32_t k23 = one << 23;                       // 2^23 in a register
    unsigned p = blockIdx.x * 256u + threadIdx.x;   // index over b in [0,8)
    unsigned wo = p % 56u;
    unsigned t1 = p / 56u;
    unsigned ho = t1 % 56u;
    unsigned t2 = t1 / 56u;          // b*128 + c, b < 8
    unsigned c  = t2 % 128u;

    // temperature: relu + 0.1; rt2 = (1/t)/ln2 shared by all 4 outputs
    float T  = temp[(c * 56u + ho) * 56u + wo];
    float tt = fmaxf(T, 0.0f) + 0.1f;
    float rt2 = __frcp_rn(tt) * 1.44269504088896340736f;

    unsigned xoff = (t2 * 112u + 2u * ho) * 112u + 2u * wo;
    unsigned base = p * 4u;

    #pragma unroll
    for (unsigned q = 0; q < 4; q++) {
        unsigned xo = xoff + q * QC;
        float2 v0 = *reinterpret_cast<const float2*>(x + xo);
        float2 v1 = *reinterpret_cast<const float2*>(x + xo + 112u);
        unsigned cb = base + q * QC;          // counter stride = 4*QO = QC
        uint32_t r0 = tf_fbits_0_42(cb + 0u, one, k23);
        uint32_t r1 = tf_fbits_0_42(cb + 1u, one, k23);
        uint32_t r2 = tf_fbits_0_42(cb + 2u, one, k23);
        uint32_t r3 = tf_fbits_0_42(cb + 3u, one, k23);
        out[p + q * QO] = argmax_pick(v0, v1, rt2, r0, r1, r2, r3);
    }
}

extern "C" void kernel_launch(void* const* d_in, const int* in_sizes, int n_in,
                              void* d_out, int out_size) {
    const float* x    = (const float*)d_in[0];   // (32,128,112,112) fp32
    const float* temp = (const float*)d_in[1];   // (128,56,56) fp32
    float* out        = (float*)d_out;           // (32,128,56,56) fp32

    // quads = 8*128*56*56 = 3,211,264 = 256 * 12544 exactly
    tdgs_pool_kernel<<<dim3(12544, 1, 1), 256>>>(x, temp, out);
}

// round 11
// speedup vs baseline: 1.0842x; 1.0842x over previous
#include <cuda_runtime.h>
#include <stdint.h>

// TDGSPooling2d: gumbel-softmax hard pooling over 2x2 patches (forward = argmax).
// out[b,c,ho,wo] = x_patch[argmax_k(x_patch[k]/temp[c,ho,wo] + g_k)]
// Noise: JAX partitionable threefry: bits[i] = o0^o1,
//   (o0,o1) = threefry2x32(key=(0,42), counter=(0,i))
//
// R11: total-issue-bound -> delete instructions.
//  (1) log1p poly path removed: pure MUFU double-log. Error audit: MUFU's
//      first-log error grows ~2^k as u -> 1-2^-k, but the win margin grows
//      ~k bits; integrated expected flips from the former poly band ~0.1.
//  (2) key injections fused: x0 = x0 + ks + x1p as ONE IADD3 (plain C so
//      ptxas fuses); x1p materialized anyway for the rotate. -4 ops/hash.
//  R10 umulhi tail reverted (was neutral-negative).

#define QC 12845056u   // x element stride AND counter stride per quarter (=4*QO)
#define QO 3211264u    // output element stride per batch-quarter (8*401408)

// add on the FMA pipe: a*one + b, one==1 but unprovable by ptxas
__device__ __forceinline__ uint32_t addf(uint32_t a, uint32_t b, uint32_t one) {
    uint32_t r;
    asm("mad.lo.u32 %0, %1, %2, %3;" : "=r"(r) : "r"(a), "r"(one), "r"(b));
    return r;
}

// ---------- threefry2x32, key=(0,42), counter (0,c1), return o0^o1 ----------
// ks0 = 0, ks1 = 42, ks2 = 0x1BD11BDA ^ 0 ^ 42 = 0x1BD11BF0
// Round: x0 += x1; x1 = rotl(x1,r) ^ x0.  Injections every 4 rounds.
// Injection+round fusion: x1p = x1 + ksB; x0 = x0 + ksA + x1p (one IADD3);
// x1 = rotl(x1p, r) ^ x0.
__device__ __forceinline__ uint32_t tf_xor_0_42(uint32_t c1, uint32_t one) {
    const uint32_t ks1 = 42u;
    const uint32_t ks2 = 0x1BD11BF0u;
    uint32_t x1 = c1 + ks1;
    uint32_t x0 = x1;                 // round-1 add with x0 = c0+ks0 = 0
    x1 = __funnelshift_l(x1, x1, 13) ^ x0;
#define R(r) { x0 = addf(x1, x0, one); x1 = __funnelshift_l(x1, x1, (r)) ^ x0; }
#define INJR(ksA, ksB, r) { uint32_t x1p = x1 + (ksB);                 \
                            x0 = x0 + (ksA) + x1p; /* IADD3 */         \
                            x1 = __funnelshift_l(x1p, x1p, (r)) ^ x0; }
    R(15) R(26) R(6)                       // rounds 2-4
    INJR(ks1, ks2 + 1u, 17)                // inject1 + round 5
    R(29) R(16) R(24)                      // rounds 6-8
    INJR(ks2, 2u, 13)                      // inject2 + round 9   (ksB = ks0+2)
    R(15) R(26) R(6)                       // rounds 10-12
    { uint32_t x1p = x1 + (ks1 + 3u);      // inject3 (x0 key = ks0 = 0) + rd 13
      x0 = addf(x1p, x0, one);
      x1 = __funnelshift_l(x1p, x1p, 17) ^ x0; }
    R(29) R(16) R(24)                      // rounds 14-16
    INJR(ks1, ks2 + 4u, 13)                // inject4 + round 17
    R(15) R(26) R(6)                       // rounds 18-20
#undef R
#undef INJR
    x0 = x0 + ks2;                         // final injection
    x1 = x1 + 5u;                          // ks0 + 5
    return x0 ^ x1;
}

// ---------- gumbel in base-2 score domain, pure MUFU ----------
// Returns L = log2(-log2(u)); caller's score w = fmaf(x, rt2, -L).
// u = bitcast(bits>>9 | 0x3f800000) - 1 (exact). u=0: w -> -inf, never
// wins; reference's clamped lane also never wins (P ~ 1e-60).
__device__ __forceinline__ float log2_negl2_u(uint32_t bits) {
    float u = __uint_as_float((bits >> 9) | 0x3f800000u) - 1.0f;
    float l1 = __log2f(u);          // <= 0
    return __log2f(-l1);            // negation is a free operand modifier
}

__device__ __forceinline__ float argmax_pick(float2 v0, float2 v1, float rt2,
                                             uint32_t r0, uint32_t r1,
                                             uint32_t r2, uint32_t r3) {
    float wb = fmaf(v0.x, rt2, -log2_negl2_u(r0));
    float xb = v0.x;
    float w;
    w = fmaf(v0.y, rt2, -log2_negl2_u(r1)); if (w > wb) { wb = w; xb = v0.y; }
    w = fmaf(v1.x, rt2, -log2_negl2_u(r2)); if (w > wb) { wb = w; xb = v1.x; }
    w = fmaf(v1.y, rt2, -log2_negl2_u(r3)); if (w > wb) { wb = w; xb = v1.y; }
    return xb;
}

__global__ __launch_bounds__(256)
void tdgs_pool_kernel(const float* __restrict__ x,
                      const float* __restrict__ temp,
                      float* __restrict__ out) {
    uint32_t one = gridDim.y;                       // == 1, opaque to ptxas
    unsigned p = blockIdx.x * 256u + threadIdx.x;   // index over b in [0,8)
    unsigned wo = p % 56u;
    unsigned t1 = p / 56u;
    unsigned ho = t1 % 56u;
    unsigned t2 = t1 / 56u;          // b*128 + c, b < 8
    unsigned c  = t2 % 128u;

    // temperature: relu + 0.1; rt2 = (1/t)/ln2 shared by all 4 outputs
    float T  = temp[(c * 56u + ho) * 56u + wo];
    float tt = fmaxf(T, 0.0f) + 0.1f;
    float rt2 = __frcp_rn(tt) * 1.44269504088896340736f;

    unsigned xoff = (t2 * 112u + 2u * ho) * 112u + 2u * wo;
    unsigned base = p * 4u;

    #pragma unroll
    for (unsigned q = 0; q < 4; q++) {
        unsigned xo = xoff + q * QC;
        float2 v0 = *reinterpret_cast<const float2*>(x + xo);
        float2 v1 = *reinterpret_cast<const float2*>(x + xo + 112u);
        unsigned cb = base + q * QC;          // counter stride = 4*QO = QC
        uint32_t r0 = tf_xor_0_42(cb + 0u, one);
        uint32_t r1 = tf_xor_0_42(cb + 1u, one);
        uint32_t r2 = tf_xor_0_42(cb + 2u, one);
        uint32_t r3 = tf_xor_0_42(cb + 3u, one);
        out[p + q * QO] = argmax_pick(v0, v1, rt2, r0, r1, r2, r3);
    }
}

extern "C" void kernel_launch(void* const* d_in, const int* in_sizes, int n_in,
                              void* d_out, int out_size) {
    const float* x    = (const float*)d_in[0];   // (32,128,112,112) fp32
    const float* temp = (const float*)d_in[1];   // (128,56,56) fp32
    float* out        = (float*)d_out;           // (32,128,56,56) fp32

    // quads = 8*128*56*56 = 3,211,264 = 256 * 12544 exactly
    tdgs_pool_kernel<<<dim3(12544, 1, 1), 256>>>(x, temp, out);
}

// round 12
// speedup vs baseline: 1.0897x; 1.0051x over previous
#include <cuda_runtime.h>
#include <stdint.h>

// TDGSPooling2d: gumbel-softmax hard pooling over 2x2 patches (forward = argmax).
// out[b,c,ho,wo] = x_patch[argmax_k(x_patch[k]/temp[c,ho,wo] + g_k)]
// Noise: JAX partitionable threefry: bits[i] = o0^o1,
//   (o0,o1) = threefry2x32(key=(0,42), counter=(0,i))
//
// R12: scheduling headroom. regs were capped at 32 (full occupancy), which
// serialized each quarter's loads+MUFU against its hash block. Now:
//  - __launch_bounds__(256, 6): 42-reg budget, ~75% occupancy
//  - all 8 patch float2 loads hoisted above the hash loop (latency decoupled)
// Math identical to R11 -> rel_err must stay exactly 1.620238e-4.

#define QC 12845056u   // x element stride AND counter stride per quarter (=4*QO)
#define QO 3211264u    // output element stride per batch-quarter (8*401408)

// add on the FMA pipe: a*one + b, one==1 but unprovable by ptxas
__device__ __forceinline__ uint32_t addf(uint32_t a, uint32_t b, uint32_t one) {
    uint32_t r;
    asm("mad.lo.u32 %0, %1, %2, %3;" : "=r"(r) : "r"(a), "r"(one), "r"(b));
    return r;
}

// ---------- threefry2x32, key=(0,42), counter (0,c1), return o0^o1 ----------
// ks0 = 0, ks1 = 42, ks2 = 0x1BD11BDA ^ 0 ^ 42 = 0x1BD11BF0
// Injection+round fusion: x1p = x1 + ksB; x0 = x0 + ksA + x1p (one IADD3);
// x1 = rotl(x1p, r) ^ x0.
__device__ __forceinline__ uint32_t tf_xor_0_42(uint32_t c1, uint32_t one) {
    const uint32_t ks1 = 42u;
    const uint32_t ks2 = 0x1BD11BF0u;
    uint32_t x1 = c1 + ks1;
    uint32_t x0 = x1;                 // round-1 add with x0 = c0+ks0 = 0
    x1 = __funnelshift_l(x1, x1, 13) ^ x0;
#define R(r) { x0 = addf(x1, x0, one); x1 = __funnelshift_l(x1, x1, (r)) ^ x0; }
#define INJR(ksA, ksB, r) { uint32_t x1p = x1 + (ksB);                 \
                            x0 = x0 + (ksA) + x1p; /* IADD3 */         \
                            x1 = __funnelshift_l(x1p, x1p, (r)) ^ x0; }
    R(15) R(26) R(6)                       // rounds 2-4
    INJR(ks1, ks2 + 1u, 17)                // inject1 + round 5
    R(29) R(16) R(24)                      // rounds 6-8
    INJR(ks2, 2u, 13)                      // inject2 + round 9   (ksB = ks0+2)
    R(15) R(26) R(6)                       // rounds 10-12
    { uint32_t x1p = x1 + (ks1 + 3u);      // inject3 (x0 key = ks0 = 0) + rd 13
      x0 = addf(x1p, x0, one);
      x1 = __funnelshift_l(x1p, x1p, 17) ^ x0; }
    R(29) R(16) R(24)                      // rounds 14-16
    INJR(ks1, ks2 + 4u, 13)                // inject4 + round 17
    R(15) R(26) R(6)                       // rounds 18-20
#undef R
#undef INJR
    x0 = x0 + ks2;                         // final injection
    x1 = x1 + 5u;                          // ks0 + 5
    return x0 ^ x1;
}

// ---------- gumbel in base-2 score domain, pure MUFU (verified R11) -------
// Returns L = log2(-log2(u)); caller's score w = fmaf(x, rt2, -L).
// u=0: w -> -inf, never wins (matches reference's clamped lane, P ~ 1e-60).
__device__ __forceinline__ float log2_negl2_u(uint32_t bits) {
    float u = __uint_as_float((bits >> 9) | 0x3f800000u) - 1.0f;
    float l1 = __log2f(u);          // <= 0
    return __log2f(-l1);            // negation is a free operand modifier
}

__device__ __forceinline__ float argmax_pick(float2 v0, float2 v1, float rt2,
                                             uint32_t r0, uint32_t r1,
                                             uint32_t r2, uint32_t r3) {
    float wb = fmaf(v0.x, rt2, -log2_negl2_u(r0));
    float xb = v0.x;
    float w;
    w = fmaf(v0.y, rt2, -log2_negl2_u(r1)); if (w > wb) { wb = w; xb = v0.y; }
    w = fmaf(v1.x, rt2, -log2_negl2_u(r2)); if (w > wb) { wb = w; xb = v1.x; }
    w = fmaf(v1.y, rt2, -log2_negl2_u(r3)); if (w > wb) { wb = w; xb = v1.y; }
    return xb;
}

__global__ __launch_bounds__(256, 6)
void tdgs_pool_kernel(const float* __restrict__ x,
                      const float* __restrict__ temp,
                      float* __restrict__ out) {
    uint32_t one = gridDim.y;                       // == 1, opaque to ptxas
    unsigned p = blockIdx.x * 256u + threadIdx.x;   // index over b in [0,8)
    unsigned wo = p % 56u;
    unsigned t1 = p / 56u;
    unsigned ho = t1 % 56u;
    unsigned t2 = t1 / 56u;          // b*128 + c, b < 8
    unsigned c  = t2 % 128u;

    // temperature: relu + 0.1; rt2 = (1/t)/ln2 shared by all 4 outputs
    float T  = temp[(c * 56u + ho) * 56u + wo];
    float tt = fmaxf(T, 0.0f) + 0.1f;
    float rt2 = __frcp_rn(tt) * 1.44269504088896340736f;

    unsigned xoff = (t2 * 112u + 2u * ho) * 112u + 2u * wo;
    unsigned base = p * 4u;

    // Hoist ALL patch loads above the compute: memory latency fully
    // decoupled from the threefry/MUFU stream.
    float2 v0[4], v1[4];
    #pragma unroll
    for (unsigned q = 0; q < 4; q++) {
        unsigned xo = xoff + q * QC;
        v0[q] = *reinterpret_cast<const float2*>(x + xo);
        v1[q] = *reinterpret_cast<const float2*>(x + xo + 112u);
    }

    #pragma unroll
    for (unsigned q = 0; q < 4; q++) {
        unsigned cb = base + q * QC;          // counter stride = 4*QO = QC
        uint32_t r0 = tf_xor_0_42(cb + 0u, one);
        uint32_t r1 = tf_xor_0_42(cb + 1u, one);
        uint32_t r2 = tf_xor_0_42(cb + 2u, one);
        uint32_t r3 = tf_xor_0_42(cb + 3u, one);
        out[p + q * QO] = argmax_pick(v0[q], v1[q], rt2, r0, r1, r2, r3);
    }
}

extern "C" void kernel_launch(void* const* d_in, const int* in_sizes, int n_in,
                              void* d_out, int out_size) {
    const float* x    = (const float*)d_in[0];   // (32,128,112,112) fp32
    const float* temp = (const float*)d_in[1];   // (128,56,56) fp32
    float* out        = (float*)d_out;           // (32,128,56,56) fp32

    // quads = 8*128*56*56 = 3,211,264 = 256 * 12544 exactly
    tdgs_pool_kernel<<<dim3(12544, 1, 1), 256>>>(x, temp, out);
}